// round 15
// baseline (speedup 1.0000x reference)
#include <cuda_runtime.h>
#include <cuda_bf16.h>
#include <cstdint>

#define LDIM 128
#define CDIM 128
#define BDIM 4
#define NST  64

__device__ float2 g_scratch[BDIM * CDIM * LDIM * LDIM];    // final conv out, 64 MiB
__device__ float2 g_scratch2[BDIM * CDIM * LDIM * LDIM];   // pass1 out (transposed), 64 MiB
__device__ float2 g_k[2][CDIM][LDIM];                      // SSM kernels
// W split planes: [mat: 0=Wr_h 1=Wr_l 2=-Wi_h 3=-Wi_l][quarter q][d*32+cl]
__device__ __nv_bfloat16 g_Wbf[4][4][4096];

typedef unsigned long long u64;

__device__ __forceinline__ u64 pk2(float lo, float hi) {
    u64 r; asm("mov.b64 %0, {%1,%2};" : "=l"(r) : "f"(lo), "f"(hi)); return r;
}
__device__ __forceinline__ void upk2(u64 v, float& lo, float& hi) {
    asm("mov.b64 {%0,%1}, %2;" : "=f"(lo), "=f"(hi) : "l"(v));
}
#define FMA2(d, a, b) asm("fma.rn.f32x2 %0, %1, %2, %0;" : "+l"(d) : "l"(a), "l"(b))

#define MMA16816(d, a, b) \
    asm volatile("mma.sync.aligned.m16n8k16.row.col.f32.bf16.bf16.f32 " \
        "{%0,%1,%2,%3}, {%4,%5,%6,%7}, {%8,%9}, {%0,%1,%2,%3};" \
        : "+f"((d)[0]), "+f"((d)[1]), "+f"((d)[2]), "+f"((d)[3]) \
        : "r"((a)[0]), "r"((a)[1]), "r"((a)[2]), "r"((a)[3]), \
          "r"((b)[0]), "r"((b)[1]))

// ---------------------------------------------------------------------------
// Kernel 1: build k0, k1.
// ---------------------------------------------------------------------------
__global__ void k_kernel(const float* __restrict__ log_A_real,
                         const float* __restrict__ A_imag,
                         const float* __restrict__ Bp_re, const float* __restrict__ Bp_im,
                         const float* __restrict__ Cp_re, const float* __restrict__ Cp_im,
                         const float* __restrict__ log_dt)
{
    int idx = blockIdx.x * blockDim.x + threadIdx.x;
    if (idx >= 2 * CDIM * LDIM) return;
    int which = idx >> 14;
    int c     = (idx >> 7) & 127;
    int l     = idx & 127;

    float dt = expf(log_dt[which * CDIM + c]);
    float fl = (float)l;
    float sr = 0.f, si = 0.f;
    int base = (which * CDIM + c) * NST;
    for (int n = 0; n < NST; ++n) {
        float Are = -expf(log_A_real[base + n]);
        float Aim = A_imag[which * NST + n];
        float br = Bp_re[base + n], bi = Bp_im[base + n];
        float cr = Cp_re[base + n], ci = Cp_im[base + n];
        float wr = cr * br - ci * bi;
        float wi = cr * bi + ci * br;
        float mag = expf(fl * dt * Are);
        float ph  = fl * dt * Aim;
        float sp, cp;
        sincosf(ph, &sp, &cp);
        sr += mag * (wr * cp - wi * sp);
        si += mag * (wr * sp + wi * cp);
    }
    g_k[which][c][l] = make_float2(sr, si);
}

// ---------------------------------------------------------------------------
// Kernel 1b: split W into bf16 hi/lo quarter-planes (Wi pre-negated).
// ---------------------------------------------------------------------------
__global__ void wprep_kernel(const float* __restrict__ W_re,
                             const float* __restrict__ W_im)
{
    int idx = blockIdx.x * blockDim.x + threadIdx.x;
    if (idx >= CDIM * CDIM) return;
    int d = idx >> 7, c = idx & 127;
    int q = c >> 5, cl = c & 31;
    int off = d * 32 + cl;
    float wr = W_re[idx], nwi = -W_im[idx];
    __nv_bfloat16 h;
    h = __float2bfloat16(wr);
    g_Wbf[0][q][off] = h;
    g_Wbf[1][q][off] = __float2bfloat16(wr - __bfloat162float(h));
    h = __float2bfloat16(nwi);
    g_Wbf[2][q][off] = h;
    g_Wbf[3][q][off] = __float2bfloat16(nwi - __bfloat162float(h));
}

// ---------------------------------------------------------------------------
// Kernel 2: generic causal row-conv pass with transposed output.
// CTA = (bc, chunk of 32 rows).  smem IN[32][137] + OUT[32][129] = 68KB
// -> 3 CTAs/SM.  8 threads/row (q = warp id), 8-output register blocking:
// 16 col-groups of 8; warp q takes {q, 15-q} -> per-warp taps = 144 (const).
// Per tap: 16 FMA2 + 3 LDS -> ~76% FMA2 issue fraction (was 62% at 4-out).
// ---------------------------------------------------------------------------
#define CIN_PITCH 137           // 8 left pad + 128 + 1
#define COUT_PITCH 129
#define CONV_SMEM ((32 * CIN_PITCH + 32 * COUT_PITCH) * 8)   // 68096 B

template<int MODE>
__global__ __launch_bounds__(256, 3) void conv_pass_kernel(
    const float* __restrict__ are, const float* __restrict__ aim,
    const float2* __restrict__ src2, float2* __restrict__ dst, int which)
{
    extern __shared__ float2 smp[];
    float2* INp  = smp;                       // [32][137], cols 0-7 zero pad
    float2* OUTs = smp + 32 * CIN_PITCH;      // [32][129]
    __shared__ u64 kpa[LDIM], kba[LDIM];

    const int bidx  = blockIdx.x;
    const int bc    = bidx >> 2;
    const int chunk = bidx & 3;
    const int c     = bc & 127;
    const int t     = threadIdx.x;

    for (int i = t; i < LDIM; i += 256) {
        float2 v = g_k[which][c][i];
        kpa[i] = pk2(v.x, v.x); kba[i] = pk2(v.y, v.y);
    }
    for (int i = t; i < 32 * 8; i += 256)
        INp[(i >> 3) * CIN_PITCH + (i & 7)] = make_float2(0.f, 0.f);

    const size_t base = (size_t)bc << 14;
    for (int i = t; i < 32 * LDIM; i += 256) {
        int rr = i >> 7, j = i & 127;
        size_t g = base + (size_t)(chunk * 32 + rr) * LDIM + j;
        float2 v;
        if (MODE == 0) v = make_float2(are[g], aim[g]);
        else           v = src2[g];
        INp[rr * CIN_PITCH + 8 + j] = v;
    }
    __syncthreads();

    const int q   = t >> 5;        // warp id 0..7 (uniform)
    const int row = t & 31;
    const u64* pp = (const u64*)INp;
    const int rbase = row * CIN_PITCH;
    const int obase = row * COUT_PITCH;
    const int grp[2] = { q, 15 - q };   // balanced: (8q+8)+(128-8q+8)=144 taps
#pragma unroll
    for (int mg = 0; mg < 2; ++mg) {
        const int j0 = 8 * grp[mg];
        const int P  = rbase + 8 + j0;
        u64 A0=0,B0=0,A1=0,B1=0,A2=0,B2=0,A3=0,B3=0;
        u64 A4=0,B4=0,A5=0,B5=0,A6=0,B6=0,A7=0,B7=0;
        u64 v0=pp[P],   v1=pp[P+1], v2=pp[P+2], v3=pp[P+3];
        u64 v4=pp[P+4], v5=pp[P+5], v6=pp[P+6], v7=pp[P+7];
        const int n = j0 + 8;                  // divisible by 8
#pragma unroll 8
        for (int i = 0; i < n; ++i) {
            u64 kp = kpa[i], kb = kba[i];
            FMA2(A0, kp, v0); FMA2(B0, kb, v0);
            FMA2(A1, kp, v1); FMA2(B1, kb, v1);
            FMA2(A2, kp, v2); FMA2(B2, kb, v2);
            FMA2(A3, kp, v3); FMA2(B3, kb, v3);
            FMA2(A4, kp, v4); FMA2(B4, kb, v4);
            FMA2(A5, kp, v5); FMA2(B5, kb, v5);
            FMA2(A6, kp, v6); FMA2(B6, kb, v6);
            FMA2(A7, kp, v7); FMA2(B7, kb, v7);
            v7=v6; v6=v5; v5=v4; v4=v3; v3=v2; v2=v1; v1=v0;
            v0 = pp[P - 1 - i];                // min index = rbase (pad 0)
        }
        float ar, ai2, br2, bi2;
        upk2(A0,ar,ai2); upk2(B0,br2,bi2); OUTs[obase+j0  ]=make_float2(ar-bi2, ai2+br2);
        upk2(A1,ar,ai2); upk2(B1,br2,bi2); OUTs[obase+j0+1]=make_float2(ar-bi2, ai2+br2);
        upk2(A2,ar,ai2); upk2(B2,br2,bi2); OUTs[obase+j0+2]=make_float2(ar-bi2, ai2+br2);
        upk2(A3,ar,ai2); upk2(B3,br2,bi2); OUTs[obase+j0+3]=make_float2(ar-bi2, ai2+br2);
        upk2(A4,ar,ai2); upk2(B4,br2,bi2); OUTs[obase+j0+4]=make_float2(ar-bi2, ai2+br2);
        upk2(A5,ar,ai2); upk2(B5,br2,bi2); OUTs[obase+j0+5]=make_float2(ar-bi2, ai2+br2);
        upk2(A6,ar,ai2); upk2(B6,br2,bi2); OUTs[obase+j0+6]=make_float2(ar-bi2, ai2+br2);
        upk2(A7,ar,ai2); upk2(B7,br2,bi2); OUTs[obase+j0+7]=make_float2(ar-bi2, ai2+br2);
    }
    __syncthreads();

    // transposed write: lanes r contiguous -> 256B coalesced; smem stride 129
    for (int i = t; i < 32 * LDIM; i += 256) {
        int col = i >> 5, r = i & 31;
        dst[base + (size_t)col * LDIM + chunk * 32 + r] = OUTs[r * COUT_PITCH + col];
    }
}

// ---------------------------------------------------------------------------
// Kernel 3 (mode 1): mix via mma.sync bf16-split GEMM (R14 proven version).
// ---------------------------------------------------------------------------
#define WQ 20
#define WPL (128 * WQ)
#define SPL (64 * WQ)
#define S_OFFB (4 * WPL)
#define MIXMMA_SMEM ((4 * WPL + 4 * SPL) * 4)

__global__ __launch_bounds__(256) void mix_mma_kernel(float* __restrict__ out)
{
    extern __shared__ __align__(16) uint32_t sw[];
    const int tid  = threadIdx.x;
    const int warp = tid >> 5, lane = tid & 31;
    const int g = lane >> 2, t = lane & 3;
    const int b  = blockIdx.x >> 8;
    const int p0 = (blockIdx.x & 255) * 64;
    const int m0 = warp * 16;

    float acc[8][4];
#pragma unroll
    for (int n = 0; n < 8; ++n)
#pragma unroll
        for (int i = 0; i < 4; ++i) acc[n][i] = 0.f;

    for (int q = 0; q < 4; ++q) {
        {
            const uint32_t* s0 = (const uint32_t*)&g_Wbf[0][q][0];
            const uint32_t* s1 = (const uint32_t*)&g_Wbf[1][q][0];
            const uint32_t* s2 = (const uint32_t*)&g_Wbf[2][q][0];
            const uint32_t* s3 = (const uint32_t*)&g_Wbf[3][q][0];
            for (int i = tid; i < 2048; i += 256) {
                int d = i >> 4, w = i & 15;
                int dst = d * WQ + w;
                sw[dst]           = s0[i];
                sw[WPL + dst]     = s1[i];
                sw[2 * WPL + dst] = s2[i];
                sw[3 * WPL + dst] = s3[i];
            }
        }
        {
            __nv_bfloat16* sb = (__nv_bfloat16*)(sw + S_OFFB);
            for (int i = tid; i < 2048; i += 256) {
                int cl = i >> 6, p = i & 63;
                float2 s = g_scratch[((size_t)(b * CDIM + q * 32 + cl) << 14) + p0 + p];
                int off = p * 40 + cl;
                __nv_bfloat16 h;
                h = __float2bfloat16(s.x);
                sb[off]        = h;
                sb[2560 + off] = __float2bfloat16(s.x - __bfloat162float(h));
                h = __float2bfloat16(s.y);
                sb[5120 + off] = h;
                sb[7680 + off] = __float2bfloat16(s.y - __bfloat162float(h));
            }
        }
        __syncthreads();

#pragma unroll
        for (int ks = 0; ks < 2; ++ks) {
            uint32_t af[4][4];
#pragma unroll
            for (int pl2 = 0; pl2 < 4; ++pl2) {
                const uint32_t* ap = sw + pl2 * WPL;
                int i0 = (m0 + g) * WQ + ks * 8 + t;
                int i1 = i0 + 8 * WQ;
                af[pl2][0] = ap[i0];     af[pl2][1] = ap[i1];
                af[pl2][2] = ap[i0 + 4]; af[pl2][3] = ap[i1 + 4];
            }
#pragma unroll
            for (int n = 0; n < 8; ++n) {
                uint32_t bf[4][2];
#pragma unroll
                for (int qq = 0; qq < 4; ++qq) {
                    const uint32_t* bp = sw + S_OFFB + qq * SPL;
                    int i0 = (n * 8 + g) * WQ + ks * 8 + t;
                    bf[qq][0] = bp[i0]; bf[qq][1] = bp[i0 + 4];
                }
                MMA16816(acc[n], af[0], bf[0]);
                MMA16816(acc[n], af[1], bf[0]);
                MMA16816(acc[n], af[0], bf[1]);
                MMA16816(acc[n], af[2], bf[2]);
                MMA16816(acc[n], af[3], bf[2]);
                MMA16816(acc[n], af[2], bf[3]);
            }
        }
        __syncthreads();
    }

#pragma unroll
    for (int n = 0; n < 8; ++n) {
        int p = p0 + n * 8 + 2 * t;
        size_t r0 = ((size_t)(b * CDIM + m0 + g) << 14) + p;
        size_t r1 = ((size_t)(b * CDIM + m0 + g + 8) << 14) + p;
        *(float2*)(out + r0) = make_float2(acc[n][0], acc[n][1]);
        *(float2*)(out + r1) = make_float2(acc[n][2], acc[n][3]);
    }
}

// ---------------------------------------------------------------------------
// Kernel 3 (mode 0, complex output): FMA2 mix (known-correct fallback).
// ---------------------------------------------------------------------------
__global__ __launch_bounds__(256) void mix_kernel(const float* __restrict__ W_re,
                                                  const float* __restrict__ W_im,
                                                  float* __restrict__ out)
{
    extern __shared__ u64 sm64[];
    u64* Wrr = sm64;
    u64* Wii = sm64 + 2048;
    u64* Sr2 = sm64 + 4096;
    u64* Si2 = sm64 + 5120;
    u64* Sn2 = sm64 + 6144;

    const int bidx = blockIdx.x;
    const int b  = bidx >> 7;
    const int p0 = (bidx & 127) * 128;
    const int tid = threadIdx.x;
    const int tx = tid & 15;
    const int ty = tid >> 4;

    u64 accre[8][4], accim[8][4];
#pragma unroll
    for (int j = 0; j < 8; ++j)
#pragma unroll
        for (int m = 0; m < 4; ++m) { accre[j][m] = 0; accim[j][m] = 0; }

    for (int cc = 0; cc < CDIM; cc += 16) {
        __syncthreads();
        for (int idx = tid; idx < 2048; idx += 256) {
            int d = idx >> 4, ci = idx & 15;
            int gidx = d * CDIM + cc + ci;
            float wr = W_re[gidx], wi = W_im[gidx];
            Wrr[(d << 4) | ci] = pk2(wr, wr);
            Wii[(d << 4) | ci] = pk2(wi, wi);
        }
        for (int idx = tid; idx < 2048; idx += 256) {
            int ci = idx >> 7, p = idx & 127;
            float2 s = g_scratch[((size_t)(b * CDIM + cc + ci) << 14) + p0 + p];
            int e = p & 63, hi = p >> 6;
            ((float*)&Sr2[(ci << 6) + e])[hi] = s.x;
            ((float*)&Si2[(ci << 6) + e])[hi] = s.y;
            ((float*)&Sn2[(ci << 6) + e])[hi] = -s.y;
        }
        __syncthreads();
#pragma unroll
        for (int ci = 0; ci < 16; ++ci) {
            u64 sr[4], si[4], sn[4];
#pragma unroll
            for (int m = 0; m < 4; ++m) {
                int e = tx + 16 * m;
                sr[m] = Sr2[(ci << 6) + e];
                si[m] = Si2[(ci << 6) + e];
                sn[m] = Sn2[(ci << 6) + e];
            }
#pragma unroll
            for (int j = 0; j < 8; ++j) {
                u64 wr2 = Wrr[((ty + 16 * j) << 4) | ci];
                u64 wi2 = Wii[((ty + 16 * j) << 4) | ci];
#pragma unroll
                for (int m = 0; m < 4; ++m) {
                    FMA2(accre[j][m], wr2, sr[m]);
                    FMA2(accre[j][m], wi2, sn[m]);
                    FMA2(accim[j][m], wr2, si[m]);
                    FMA2(accim[j][m], wi2, sr[m]);
                }
            }
        }
    }

    float2* out2 = (float2*)out;
#pragma unroll
    for (int j = 0; j < 8; ++j) {
        int d = ty + 16 * j;
        size_t rowb = ((size_t)(b * CDIM + d) << 14) + p0;
#pragma unroll
        for (int m = 0; m < 4; ++m) {
            float reA, reB, imA, imB;
            upk2(accre[j][m], reA, reB);
            upk2(accim[j][m], imA, imB);
            out2[rowb + tx + 16 * m]      = make_float2(reA, imA);
            out2[rowb + tx + 16 * m + 64] = make_float2(reB, imB);
        }
    }
}

// ---------------------------------------------------------------------------
extern "C" void kernel_launch(void* const* d_in, const int* in_sizes, int n_in,
                              void* d_out, int out_size)
{
    const float* big[2]   = {nullptr, nullptr};
    const float* mid[16];
    const float* a_imag_p = nullptr;
    const float* log_dt_p = nullptr;
    int nbig = 0, nmid = 0, a_pos = -1;

    for (int i = 0; i < n_in; ++i) {
        const float* p = (const float*)d_in[i];
        int sz = in_sizes[i];
        if (sz == BDIM * CDIM * LDIM * LDIM) { if (nbig < 2) big[nbig++] = p; }
        else if (sz == 2 * NST)              { a_imag_p = p; a_pos = i; }
        else if (sz == 2 * CDIM)             { log_dt_p = p; }
        else if (sz == CDIM * CDIM && nmid < 16) { mid[nmid++] = p; }
    }
    if (nbig != 2 || !a_imag_p || !log_dt_p || nmid < 7) return;

    const float *u_re = big[0], *u_im = big[1];
    const float *log_A_real, *Bp_re, *Bp_im, *Cp_re, *Cp_im, *W_re, *W_im;
    if (a_pos == 0) {
        Bp_im = mid[0]; Bp_re = mid[1]; Cp_im = mid[2]; Cp_re = mid[3];
        W_im  = mid[4]; W_re  = mid[5]; log_A_real = mid[6];
        u_im = big[0]; u_re = big[1];
    } else {
        log_A_real = mid[0]; Bp_re = mid[1]; Bp_im = mid[2];
        Cp_re = mid[3]; Cp_im = mid[4]; W_re = mid[5]; W_im = mid[6];
    }

    const int mode = (out_size >= 2 * BDIM * CDIM * LDIM * LDIM) ? 0 : 1;

    k_kernel<<<128, 256>>>(log_A_real, a_imag_p, Bp_re, Bp_im, Cp_re, Cp_im, log_dt_p);

    float2* scr  = nullptr;
    float2* scr2 = nullptr;
    cudaGetSymbolAddress((void**)&scr,  g_scratch);
    cudaGetSymbolAddress((void**)&scr2, g_scratch2);

    cudaFuncSetAttribute(conv_pass_kernel<0>, cudaFuncAttributeMaxDynamicSharedMemorySize, CONV_SMEM);
    cudaFuncSetAttribute(conv_pass_kernel<1>, cudaFuncAttributeMaxDynamicSharedMemorySize, CONV_SMEM);
    conv_pass_kernel<0><<<BDIM * CDIM * 4, 256, CONV_SMEM>>>(u_re, u_im, nullptr, scr2, 1);
    conv_pass_kernel<1><<<BDIM * CDIM * 4, 256, CONV_SMEM>>>(nullptr, nullptr, scr2, scr, 0);

    if (mode == 1) {
        wprep_kernel<<<64, 256>>>(W_re, W_im);
        cudaFuncSetAttribute(mix_mma_kernel, cudaFuncAttributeMaxDynamicSharedMemorySize, MIXMMA_SMEM);
        mix_mma_kernel<<<BDIM * 256, 256, MIXMMA_SMEM>>>((float*)d_out);
    } else {
        const int mix_smem = 7168 * (int)sizeof(u64);
        cudaFuncSetAttribute(mix_kernel, cudaFuncAttributeMaxDynamicSharedMemorySize, mix_smem);
        mix_kernel<<<BDIM * 128, 256, mix_smem>>>(W_re, W_im, (float*)d_out);
    }
}

// round 16
// speedup vs baseline: 1.0852x; 1.0852x over previous
#include <cuda_runtime.h>
#include <cuda_bf16.h>
#include <cstdint>

#define LDIM 128
#define CDIM 128
#define BDIM 4
#define NST  64

__device__ float2 g_scratch[BDIM * CDIM * LDIM * LDIM];    // final conv out, 64 MiB
__device__ float2 g_scratch2[BDIM * CDIM * LDIM * LDIM];   // pass1 out (transposed), 64 MiB
__device__ float2 g_k[2][CDIM][LDIM];                      // SSM kernels
// W split planes: [mat: 0=Wr_h 1=Wr_l 2=-Wi_h 3=-Wi_l][quarter q][d*32+cl]
__device__ __nv_bfloat16 g_Wbf[4][4][4096];

typedef unsigned long long u64;

__device__ __forceinline__ u64 pk2(float lo, float hi) {
    u64 r; asm("mov.b64 %0, {%1,%2};" : "=l"(r) : "f"(lo), "f"(hi)); return r;
}
__device__ __forceinline__ void upk2(u64 v, float& lo, float& hi) {
    asm("mov.b64 {%0,%1}, %2;" : "=f"(lo), "=f"(hi) : "l"(v));
}
#define FMA2(d, a, b) asm("fma.rn.f32x2 %0, %1, %2, %0;" : "+l"(d) : "l"(a), "l"(b))

#define MMA16816(d, a, b) \
    asm volatile("mma.sync.aligned.m16n8k16.row.col.f32.bf16.bf16.f32 " \
        "{%0,%1,%2,%3}, {%4,%5,%6,%7}, {%8,%9}, {%0,%1,%2,%3};" \
        : "+f"((d)[0]), "+f"((d)[1]), "+f"((d)[2]), "+f"((d)[3]) \
        : "r"((a)[0]), "r"((a)[1]), "r"((a)[2]), "r"((a)[3]), \
          "r"((b)[0]), "r"((b)[1]))

// ---------------------------------------------------------------------------
// Kernel 1: build k0, k1.  2 threads per output (each sums 32 states),
// combined with one shfl_xor.
// ---------------------------------------------------------------------------
__global__ void k_kernel(const float* __restrict__ log_A_real,
                         const float* __restrict__ A_imag,
                         const float* __restrict__ Bp_re, const float* __restrict__ Bp_im,
                         const float* __restrict__ Cp_re, const float* __restrict__ Cp_im,
                         const float* __restrict__ log_dt)
{
    int gidx = blockIdx.x * blockDim.x + threadIdx.x;
    if (gidx >= 2 * 2 * CDIM * LDIM) return;
    int idx  = gidx >> 1;           // output index
    int half = gidx & 1;            // which 32 states
    int which = idx >> 14;
    int c     = (idx >> 7) & 127;
    int l     = idx & 127;

    float dt = expf(log_dt[which * CDIM + c]);
    float fl = (float)l;
    float sr = 0.f, si = 0.f;
    int base = (which * CDIM + c) * NST + half * 32;
    int abase = which * NST + half * 32;
    for (int n = 0; n < 32; ++n) {
        float Are = -expf(log_A_real[base + n]);
        float Aim = A_imag[abase + n];
        float br = Bp_re[base + n], bi = Bp_im[base + n];
        float cr = Cp_re[base + n], ci = Cp_im[base + n];
        float wr = cr * br - ci * bi;
        float wi = cr * bi + ci * br;
        float mag = expf(fl * dt * Are);
        float ph  = fl * dt * Aim;
        float sp, cp;
        sincosf(ph, &sp, &cp);
        sr += mag * (wr * cp - wi * sp);
        si += mag * (wr * sp + wi * cp);
    }
    // combine the two halves (lanes differ only in bit 0)
    sr += __shfl_xor_sync(0xFFFFFFFFu, sr, 1);
    si += __shfl_xor_sync(0xFFFFFFFFu, si, 1);
    if (half == 0) g_k[which][c][l] = make_float2(sr, si);
}

// ---------------------------------------------------------------------------
// Kernel 1b: split W into bf16 hi/lo quarter-planes (Wi pre-negated).
// ---------------------------------------------------------------------------
__global__ void wprep_kernel(const float* __restrict__ W_re,
                             const float* __restrict__ W_im)
{
    int idx = blockIdx.x * blockDim.x + threadIdx.x;
    if (idx >= CDIM * CDIM) return;
    int d = idx >> 7, c = idx & 127;
    int q = c >> 5, cl = c & 31;
    int off = d * 32 + cl;
    float wr = W_re[idx], nwi = -W_im[idx];
    __nv_bfloat16 h;
    h = __float2bfloat16(wr);
    g_Wbf[0][q][off] = h;
    g_Wbf[1][q][off] = __float2bfloat16(wr - __bfloat162float(h));
    h = __float2bfloat16(nwi);
    g_Wbf[2][q][off] = h;
    g_Wbf[3][q][off] = __float2bfloat16(nwi - __bfloat162float(h));
}

// ---------------------------------------------------------------------------
// Kernel 2: generic causal row-conv pass with transposed output (R14 proven).
// CTA = (bc, chunk of 32 rows).  smem IN[32][133] + OUT[32][129] = 67KB
// -> 3 CTAs/SM.  8 threads/row, q = warp id; balanced groups {q,15-q,16+q,31-q}.
// ---------------------------------------------------------------------------
#define CIN_PITCH 133
#define COUT_PITCH 129
#define CONV_SMEM ((32 * CIN_PITCH + 32 * COUT_PITCH) * 8)   // 67072 B

template<int MODE>
__global__ __launch_bounds__(256, 3) void conv_pass_kernel(
    const float* __restrict__ are, const float* __restrict__ aim,
    const float2* __restrict__ src2, float2* __restrict__ dst, int which)
{
    extern __shared__ float2 smp[];
    float2* INp  = smp;                       // [32][133], cols 0-3 zero pad
    float2* OUTs = smp + 32 * CIN_PITCH;      // [32][129]
    __shared__ u64 kpa[LDIM], kba[LDIM];

    const int bidx  = blockIdx.x;
    const int bc    = bidx >> 2;
    const int chunk = bidx & 3;
    const int c     = bc & 127;
    const int t     = threadIdx.x;

    for (int i = t; i < LDIM; i += 256) {
        float2 v = g_k[which][c][i];
        kpa[i] = pk2(v.x, v.x); kba[i] = pk2(v.y, v.y);
    }
    for (int i = t; i < 32 * 4; i += 256)
        INp[(i >> 2) * CIN_PITCH + (i & 3)] = make_float2(0.f, 0.f);

    const size_t base = (size_t)bc << 14;
    for (int i = t; i < 32 * LDIM; i += 256) {
        int rr = i >> 7, j = i & 127;
        size_t g = base + (size_t)(chunk * 32 + rr) * LDIM + j;
        float2 v;
        if (MODE == 0) v = make_float2(are[g], aim[g]);
        else           v = src2[g];
        INp[rr * CIN_PITCH + 4 + j] = v;
    }
    __syncthreads();

    const int q   = t >> 5;        // warp id 0..7 (uniform)
    const int row = t & 31;
    const u64* pp = (const u64*)INp;
    const int rbase = row * CIN_PITCH;
    const int obase = row * COUT_PITCH;
    const int grp[4] = { q, 15 - q, 16 + q, 31 - q };   // balanced assignment
#pragma unroll
    for (int mg = 0; mg < 4; ++mg) {
        const int j0 = 4 * grp[mg];
        const int P  = rbase + 4 + j0;
        u64 A0 = 0, B0 = 0, A1 = 0, B1 = 0, A2 = 0, B2 = 0, A3 = 0, B3 = 0;
        u64 v0 = pp[P], v1 = pp[P + 1], v2 = pp[P + 2], v3 = pp[P + 3];
        const int n = j0 + 4;                  // divisible by 4
#pragma unroll 4
        for (int i = 0; i < n; ++i) {
            u64 kp = kpa[i], kb = kba[i];
            FMA2(A0, kp, v0); FMA2(B0, kb, v0);
            FMA2(A1, kp, v1); FMA2(B1, kb, v1);
            FMA2(A2, kp, v2); FMA2(B2, kb, v2);
            FMA2(A3, kp, v3); FMA2(B3, kb, v3);
            v3 = v2; v2 = v1; v1 = v0; v0 = pp[P - 1 - i];
        }
        float ar, ai2, br2, bi2;
        upk2(A0, ar, ai2); upk2(B0, br2, bi2);
        OUTs[obase + j0]     = make_float2(ar - bi2, ai2 + br2);
        upk2(A1, ar, ai2); upk2(B1, br2, bi2);
        OUTs[obase + j0 + 1] = make_float2(ar - bi2, ai2 + br2);
        upk2(A2, ar, ai2); upk2(B2, br2, bi2);
        OUTs[obase + j0 + 2] = make_float2(ar - bi2, ai2 + br2);
        upk2(A3, ar, ai2); upk2(B3, br2, bi2);
        OUTs[obase + j0 + 3] = make_float2(ar - bi2, ai2 + br2);
    }
    __syncthreads();

    // transposed write: lanes r contiguous -> 256B coalesced; smem stride 129
    for (int i = t; i < 32 * LDIM; i += 256) {
        int col = i >> 5, r = i & 31;
        dst[base + (size_t)col * LDIM + chunk * 32 + r] = OUTs[r * COUT_PITCH + col];
    }
}

// ---------------------------------------------------------------------------
// Kernel 3 (mode 1): mix via mma.sync bf16-split GEMM, software-pipelined:
// the g_scratch LDGs for quarter q+1 are issued into registers BEFORE the
// MMA phase of quarter q; conversion/STS happens after the post-MMA barrier.
// ---------------------------------------------------------------------------
#define WQ 20
#define WPL (128 * WQ)
#define SPL (64 * WQ)
#define S_OFFB (4 * WPL)
#define MIXMMA_SMEM ((4 * WPL + 4 * SPL) * 4)

__device__ __forceinline__ void mix_load_w(uint32_t* sw, int q, int tid) {
    const uint32_t* s0 = (const uint32_t*)&g_Wbf[0][q][0];
    const uint32_t* s1 = (const uint32_t*)&g_Wbf[1][q][0];
    const uint32_t* s2 = (const uint32_t*)&g_Wbf[2][q][0];
    const uint32_t* s3 = (const uint32_t*)&g_Wbf[3][q][0];
    for (int i = tid; i < 2048; i += 256) {
        int d = i >> 4, w = i & 15;
        int dst = d * WQ + w;
        sw[dst]           = s0[i];
        sw[WPL + dst]     = s1[i];
        sw[2 * WPL + dst] = s2[i];
        sw[3 * WPL + dst] = s3[i];
    }
}
__device__ __forceinline__ void mix_store_s(uint32_t* sw, const float2* pf, int tid) {
    __nv_bfloat16* sb = (__nv_bfloat16*)(sw + S_OFFB);
#pragma unroll
    for (int j = 0; j < 8; ++j) {
        int i = tid + j * 256;
        int cl = i >> 6, p = i & 63;
        int off = p * 40 + cl;
        float2 s = pf[j];
        __nv_bfloat16 h;
        h = __float2bfloat16(s.x);
        sb[off]        = h;
        sb[2560 + off] = __float2bfloat16(s.x - __bfloat162float(h));
        h = __float2bfloat16(s.y);
        sb[5120 + off] = h;
        sb[7680 + off] = __float2bfloat16(s.y - __bfloat162float(h));
    }
}

__global__ __launch_bounds__(256) void mix_mma_kernel(float* __restrict__ out)
{
    extern __shared__ __align__(16) uint32_t sw[];
    const int tid  = threadIdx.x;
    const int warp = tid >> 5, lane = tid & 31;
    const int g = lane >> 2, t = lane & 3;
    const int b  = blockIdx.x >> 8;
    const int p0 = (blockIdx.x & 255) * 64;
    const int m0 = warp * 16;

    float acc[8][4];
#pragma unroll
    for (int n = 0; n < 8; ++n)
#pragma unroll
        for (int i = 0; i < 4; ++i) acc[n][i] = 0.f;

    // prologue: W[0] + S[0] direct
    mix_load_w(sw, 0, tid);
    {
        float2 pf[8];
#pragma unroll
        for (int j = 0; j < 8; ++j) {
            int i = tid + j * 256;
            int cl = i >> 6, p = i & 63;
            pf[j] = g_scratch[((size_t)(b * CDIM + cl) << 14) + p0 + p];
        }
        mix_store_s(sw, pf, tid);
    }
    __syncthreads();

    for (int q = 0; q < 4; ++q) {
        // prefetch next quarter's scratch into registers (LDG in flight over MMA)
        float2 pf[8];
        if (q < 3) {
#pragma unroll
            for (int j = 0; j < 8; ++j) {
                int i = tid + j * 256;
                int cl = i >> 6, p = i & 63;
                pf[j] = g_scratch[((size_t)(b * CDIM + (q + 1) * 32 + cl) << 14) + p0 + p];
            }
        }

#pragma unroll
        for (int ks = 0; ks < 2; ++ks) {
            uint32_t af[4][4];
#pragma unroll
            for (int pl2 = 0; pl2 < 4; ++pl2) {
                const uint32_t* ap = sw + pl2 * WPL;
                int i0 = (m0 + g) * WQ + ks * 8 + t;
                int i1 = i0 + 8 * WQ;
                af[pl2][0] = ap[i0];     af[pl2][1] = ap[i1];
                af[pl2][2] = ap[i0 + 4]; af[pl2][3] = ap[i1 + 4];
            }
#pragma unroll
            for (int n = 0; n < 8; ++n) {
                uint32_t bf[4][2];
#pragma unroll
                for (int qq = 0; qq < 4; ++qq) {
                    const uint32_t* bp = sw + S_OFFB + qq * SPL;
                    int i0 = (n * 8 + g) * WQ + ks * 8 + t;
                    bf[qq][0] = bp[i0]; bf[qq][1] = bp[i0 + 4];
                }
                MMA16816(acc[n], af[0], bf[0]);
                MMA16816(acc[n], af[1], bf[0]);
                MMA16816(acc[n], af[0], bf[1]);
                MMA16816(acc[n], af[2], bf[2]);
                MMA16816(acc[n], af[3], bf[2]);
                MMA16816(acc[n], af[2], bf[3]);
            }
        }
        __syncthreads();            // MMA done reading smem
        if (q < 3) {
            mix_load_w(sw, q + 1, tid);
            mix_store_s(sw, pf, tid);
            __syncthreads();
        }
    }

#pragma unroll
    for (int n = 0; n < 8; ++n) {
        int p = p0 + n * 8 + 2 * t;
        size_t r0 = ((size_t)(b * CDIM + m0 + g) << 14) + p;
        size_t r1 = ((size_t)(b * CDIM + m0 + g + 8) << 14) + p;
        *(float2*)(out + r0) = make_float2(acc[n][0], acc[n][1]);
        *(float2*)(out + r1) = make_float2(acc[n][2], acc[n][3]);
    }
}

// ---------------------------------------------------------------------------
// Kernel 3 (mode 0, complex output): FMA2 mix (known-correct fallback).
// ---------------------------------------------------------------------------
__global__ __launch_bounds__(256) void mix_kernel(const float* __restrict__ W_re,
                                                  const float* __restrict__ W_im,
                                                  float* __restrict__ out)
{
    extern __shared__ u64 sm64[];
    u64* Wrr = sm64;
    u64* Wii = sm64 + 2048;
    u64* Sr2 = sm64 + 4096;
    u64* Si2 = sm64 + 5120;
    u64* Sn2 = sm64 + 6144;

    const int bidx = blockIdx.x;
    const int b  = bidx >> 7;
    const int p0 = (bidx & 127) * 128;
    const int tid = threadIdx.x;
    const int tx = tid & 15;
    const int ty = tid >> 4;

    u64 accre[8][4], accim[8][4];
#pragma unroll
    for (int j = 0; j < 8; ++j)
#pragma unroll
        for (int m = 0; m < 4; ++m) { accre[j][m] = 0; accim[j][m] = 0; }

    for (int cc = 0; cc < CDIM; cc += 16) {
        __syncthreads();
        for (int idx = tid; idx < 2048; idx += 256) {
            int d = idx >> 4, ci = idx & 15;
            int gidx = d * CDIM + cc + ci;
            float wr = W_re[gidx], wi = W_im[gidx];
            Wrr[(d << 4) | ci] = pk2(wr, wr);
            Wii[(d << 4) | ci] = pk2(wi, wi);
        }
        for (int idx = tid; idx < 2048; idx += 256) {
            int ci = idx >> 7, p = idx & 127;
            float2 s = g_scratch[((size_t)(b * CDIM + cc + ci) << 14) + p0 + p];
            int e = p & 63, hi = p >> 6;
            ((float*)&Sr2[(ci << 6) + e])[hi] = s.x;
            ((float*)&Si2[(ci << 6) + e])[hi] = s.y;
            ((float*)&Sn2[(ci << 6) + e])[hi] = -s.y;
        }
        __syncthreads();
#pragma unroll
        for (int ci = 0; ci < 16; ++ci) {
            u64 sr[4], si[4], sn[4];
#pragma unroll
            for (int m = 0; m < 4; ++m) {
                int e = tx + 16 * m;
                sr[m] = Sr2[(ci << 6) + e];
                si[m] = Si2[(ci << 6) + e];
                sn[m] = Sn2[(ci << 6) + e];
            }
#pragma unroll
            for (int j = 0; j < 8; ++j) {
                u64 wr2 = Wrr[((ty + 16 * j) << 4) | ci];
                u64 wi2 = Wii[((ty + 16 * j) << 4) | ci];
#pragma unroll
                for (int m = 0; m < 4; ++m) {
                    FMA2(accre[j][m], wr2, sr[m]);
                    FMA2(accre[j][m], wi2, sn[m]);
                    FMA2(accim[j][m], wr2, si[m]);
                    FMA2(accim[j][m], wi2, sr[m]);
                }
            }
        }
    }

    float2* out2 = (float2*)out;
#pragma unroll
    for (int j = 0; j < 8; ++j) {
        int d = ty + 16 * j;
        size_t rowb = ((size_t)(b * CDIM + d) << 14) + p0;
#pragma unroll
        for (int m = 0; m < 4; ++m) {
            float reA, reB, imA, imB;
            upk2(accre[j][m], reA, reB);
            upk2(accim[j][m], imA, imB);
            out2[rowb + tx + 16 * m]      = make_float2(reA, imA);
            out2[rowb + tx + 16 * m + 64] = make_float2(reB, imB);
        }
    }
}

// ---------------------------------------------------------------------------
extern "C" void kernel_launch(void* const* d_in, const int* in_sizes, int n_in,
                              void* d_out, int out_size)
{
    const float* big[2]   = {nullptr, nullptr};
    const float* mid[16];
    const float* a_imag_p = nullptr;
    const float* log_dt_p = nullptr;
    int nbig = 0, nmid = 0, a_pos = -1;

    for (int i = 0; i < n_in; ++i) {
        const float* p = (const float*)d_in[i];
        int sz = in_sizes[i];
        if (sz == BDIM * CDIM * LDIM * LDIM) { if (nbig < 2) big[nbig++] = p; }
        else if (sz == 2 * NST)              { a_imag_p = p; a_pos = i; }
        else if (sz == 2 * CDIM)             { log_dt_p = p; }
        else if (sz == CDIM * CDIM && nmid < 16) { mid[nmid++] = p; }
    }
    if (nbig != 2 || !a_imag_p || !log_dt_p || nmid < 7) return;

    const float *u_re = big[0], *u_im = big[1];
    const float *log_A_real, *Bp_re, *Bp_im, *Cp_re, *Cp_im, *W_re, *W_im;
    if (a_pos == 0) {
        Bp_im = mid[0]; Bp_re = mid[1]; Cp_im = mid[2]; Cp_re = mid[3];
        W_im  = mid[4]; W_re  = mid[5]; log_A_real = mid[6];
        u_im = big[0]; u_re = big[1];
    } else {
        log_A_real = mid[0]; Bp_re = mid[1]; Bp_im = mid[2];
        Cp_re = mid[3]; Cp_im = mid[4]; W_re = mid[5]; W_im = mid[6];
    }

    const int mode = (out_size >= 2 * BDIM * CDIM * LDIM * LDIM) ? 0 : 1;

    k_kernel<<<256, 256>>>(log_A_real, a_imag_p, Bp_re, Bp_im, Cp_re, Cp_im, log_dt_p);

    float2* scr  = nullptr;
    float2* scr2 = nullptr;
    cudaGetSymbolAddress((void**)&scr,  g_scratch);
    cudaGetSymbolAddress((void**)&scr2, g_scratch2);

    cudaFuncSetAttribute(conv_pass_kernel<0>, cudaFuncAttributeMaxDynamicSharedMemorySize, CONV_SMEM);
    cudaFuncSetAttribute(conv_pass_kernel<1>, cudaFuncAttributeMaxDynamicSharedMemorySize, CONV_SMEM);
    conv_pass_kernel<0><<<BDIM * CDIM * 4, 256, CONV_SMEM>>>(u_re, u_im, nullptr, scr2, 1);
    conv_pass_kernel<1><<<BDIM * CDIM * 4, 256, CONV_SMEM>>>(nullptr, nullptr, scr2, scr, 0);

    if (mode == 1) {
        wprep_kernel<<<64, 256>>>(W_re, W_im);
        cudaFuncSetAttribute(mix_mma_kernel, cudaFuncAttributeMaxDynamicSharedMemorySize, MIXMMA_SMEM);
        mix_mma_kernel<<<BDIM * 256, 256, MIXMMA_SMEM>>>((float*)d_out);
    } else {
        const int mix_smem = 7168 * (int)sizeof(u64);
        cudaFuncSetAttribute(mix_kernel, cudaFuncAttributeMaxDynamicSharedMemorySize, mix_smem);
        mix_kernel<<<BDIM * 128, 256, mix_smem>>>(W_re, W_im, (float*)d_out);
    }
}